// round 12
// baseline (speedup 1.0000x reference)
#include <cuda_runtime.h>

#define B_   256
#define C_   3
#define H_   224
#define W_   224
#define HW_  (H_ * W_)          // 50176
#define HW4  (HW_ / 4)          // 12544 float4 per plane
#define NSL  49                 // slices per image (CTAs in x)

#define GW0 0.2989f
#define GW1 0.587f
#define GW2 0.114f

// Deterministic scratch: per-(image,slice) channel partial sums.
__device__ float g_part[B_ * NSL * 3];

// ---------------------------------------------------------------------------
// Kernel A: read input ONCE; per-slice channel sums. Non-contrast images are
// finished here (clip(aug(x)*br)). Contrast-image input is read evict-NORMAL
// (__ldcg) so it survives in L2 for kernel C. Triggers programmatic launch
// completion right after the g_part store so C can overlap A's store tail.
// ---------------------------------------------------------------------------
__global__ __launch_bounds__(256) void sum_and_easy_kernel(
    const float* __restrict__ x,
    const float* __restrict__ brightness,
    const int*   __restrict__ flip_mask,
    const int*   __restrict__ gray_mask,
    const int*   __restrict__ contrast_apply,
    float*       __restrict__ out)
{
    const int b   = blockIdx.y;
    const int sl  = blockIdx.x;
    const int tid = threadIdx.x;
    const int p   = sl * 256 + tid;                      // < HW4 (49*256)

    const float br   = brightness[b];
    const bool  flip = flip_mask[b] != 0;
    const bool  gray = gray_mask[b] != 0;
    const bool  ctr  = contrast_apply[b] != 0;

    // flip-aware source (sum is flip-invariant)
    const int pix = p * 4;
    const int h   = pix / W_;
    const int w   = pix - h * W_;
    const int sp4 = flip ? ((h * W_ + (W_ - 4 - w)) >> 2) : p;

    const float4* __restrict__ in4 =
        reinterpret_cast<const float4*>(x) + (size_t)b * 3 * HW4;

    float4 v0, v1, v2;
    if (ctr) {      // keep resident in L2 for kernel C
        v0 = __ldcg(&in4[0 * HW4 + sp4]);
        v1 = __ldcg(&in4[1 * HW4 + sp4]);
        v2 = __ldcg(&in4[2 * HW4 + sp4]);
    } else {        // dead after this kernel
        v0 = __ldcs(&in4[0 * HW4 + sp4]);
        v1 = __ldcs(&in4[1 * HW4 + sp4]);
        v2 = __ldcs(&in4[2 * HW4 + sp4]);
    }

    // per-channel partial sums of ORIGINAL x
    float s0 = (v0.x + v0.y) + (v0.z + v0.w);
    float s1 = (v1.x + v1.y) + (v1.z + v1.w);
    float s2 = (v2.x + v2.y) + (v2.z + v2.w);
    #pragma unroll
    for (int o = 16; o; o >>= 1) {
        s0 += __shfl_xor_sync(~0u, s0, o);
        s1 += __shfl_xor_sync(~0u, s1, o);
        s2 += __shfl_xor_sync(~0u, s2, o);
    }
    __shared__ float red[3][8];
    if ((tid & 31) == 0) {
        red[0][tid >> 5] = s0; red[1][tid >> 5] = s1; red[2][tid >> 5] = s2;
    }
    __syncthreads();
    if (tid == 0) {
        float a0 = 0.f, a1 = 0.f, a2 = 0.f;
        #pragma unroll
        for (int q = 0; q < 8; q++) { a0 += red[0][q]; a1 += red[1][q]; a2 += red[2][q]; }
        const int off = (b * NSL + sl) * 3;
        g_part[off + 0] = a0; g_part[off + 1] = a1; g_part[off + 2] = a2;
    }

    // g_part for this CTA is committed -> let kernel C begin launching.
    cudaTriggerProgrammaticLaunchCompletion();

    if (ctr) return;                                     // finished in kernel C

    // ---- no-contrast path: out = clip(aug(x)*br) ----
    if (flip) {
        float t;
        t = v0.x; v0.x = v0.w; v0.w = t;  t = v0.y; v0.y = v0.z; v0.z = t;
        t = v1.x; v1.x = v1.w; v1.w = t;  t = v1.y; v1.y = v1.z; v1.z = t;
        t = v2.x; v2.x = v2.w; v2.w = t;  t = v2.y; v2.y = v2.z; v2.z = t;
    }
    if (gray) {
        float4 g;
        g.x = GW0 * v0.x + GW1 * v1.x + GW2 * v2.x;
        g.y = GW0 * v0.y + GW1 * v1.y + GW2 * v2.y;
        g.z = GW0 * v0.z + GW1 * v1.z + GW2 * v2.z;
        g.w = GW0 * v0.w + GW1 * v1.w + GW2 * v2.w;
        v0 = g; v1 = g; v2 = g;
    }
    #define XFB(v)                                                           \
        v.x = fminf(fmaxf(v.x * br, -2.5f), 2.5f);                           \
        v.y = fminf(fmaxf(v.y * br, -2.5f), 2.5f);                           \
        v.z = fminf(fmaxf(v.z * br, -2.5f), 2.5f);                           \
        v.w = fminf(fmaxf(v.w * br, -2.5f), 2.5f);
    XFB(v0) XFB(v1) XFB(v2)
    #undef XFB

    float4* __restrict__ out4 =
        reinterpret_cast<float4*>(out) + (size_t)b * 3 * HW4;
    __stcs(&out4[0 * HW4 + p], v0);
    __stcs(&out4[1 * HW4 + p], v1);
    __stcs(&out4[2 * HW4 + p], v2);
}

// ---------------------------------------------------------------------------
// Kernel C: contrast images only. Input loads are issued FIRST (x is not
// produced by A — safe pre-sync), then cudaGridDependencySynchronize() gates
// only the g_part reduction. Reduction is cooperative per CTA (3 warps).
// ---------------------------------------------------------------------------
__global__ __launch_bounds__(256) void contrast_kernel(
    const float* __restrict__ x,
    const float* __restrict__ brightness,
    const float* __restrict__ contrast_factor,
    const int*   __restrict__ flip_mask,
    const int*   __restrict__ gray_mask,
    const int*   __restrict__ contrast_apply,
    float*       __restrict__ out)
{
    const int b = blockIdx.y;
    if (contrast_apply[b] == 0) {
        cudaGridDependencySynchronize();                 // keep PDL semantics sane
        return;
    }

    const int tid = threadIdx.x;
    const int p   = blockIdx.x * 256 + tid;

    const float br   = brightness[b];
    const bool  flip = flip_mask[b] != 0;
    const bool  gray = gray_mask[b] != 0;
    const float cf   = contrast_factor[b];

    // ---- issue main input loads EARLY (x is read-only; L2-hot from A) ----
    const int pix = p * 4;
    const int h   = pix / W_;
    const int w   = pix - h * W_;
    const int sp4 = flip ? ((h * W_ + (W_ - 4 - w)) >> 2) : p;

    const float4* __restrict__ in4 =
        reinterpret_cast<const float4*>(x) + (size_t)b * 3 * HW4;
    float4 v0 = __ldcs(&in4[0 * HW4 + sp4]);
    float4 v1 = __ldcs(&in4[1 * HW4 + sp4]);
    float4 v2 = __ldcs(&in4[2 * HW4 + sp4]);

    // ---- wait for A's g_part, then cooperative per-CTA mean reduction ----
    cudaGridDependencySynchronize();

    __shared__ float sm_mean[3];
    if (tid < 96) {
        const int c    = tid >> 5;
        const int lane = tid & 31;
        float s = 0.f;
        if (lane < NSL)      s  = g_part[(b * NSL + lane) * 3 + c];
        if (lane + 32 < NSL) s += g_part[(b * NSL + lane + 32) * 3 + c];
        #pragma unroll
        for (int o = 16; o; o >>= 1)
            s += __shfl_xor_sync(~0u, s, o);
        if (lane == 0)
            sm_mean[c] = s * (1.0f / (float)HW_);
    }
    __syncthreads();

    const float m0 = sm_mean[0];
    const float m1 = sm_mean[1];
    const float m2 = sm_mean[2];
    const float gm = GW0 * m0 + GW1 * m1 + GW2 * m2;

    const float mm0 = (gray ? gm : m0) * br;
    const float mm1 = (gray ? gm : m1) * br;
    const float mm2 = (gray ? gm : m2) * br;

    const float scale = br * cf;
    const float omcf  = 1.0f - cf;
    const float off0 = mm0 * omcf;
    const float off1 = mm1 * omcf;
    const float off2 = mm2 * omcf;

    if (flip) {
        float t;
        t = v0.x; v0.x = v0.w; v0.w = t;  t = v0.y; v0.y = v0.z; v0.z = t;
        t = v1.x; v1.x = v1.w; v1.w = t;  t = v1.y; v1.y = v1.z; v1.z = t;
        t = v2.x; v2.x = v2.w; v2.w = t;  t = v2.y; v2.y = v2.z; v2.z = t;
    }
    if (gray) {
        float4 g;
        g.x = GW0 * v0.x + GW1 * v1.x + GW2 * v2.x;
        g.y = GW0 * v0.y + GW1 * v1.y + GW2 * v2.y;
        g.z = GW0 * v0.z + GW1 * v1.z + GW2 * v2.z;
        g.w = GW0 * v0.w + GW1 * v1.w + GW2 * v2.w;
        v0 = g; v1 = g; v2 = g;
    }

    #define XFORM(v, off)                                                    \
        v.x = fminf(fmaxf(fmaf(v.x, scale, off), -2.5f), 2.5f);             \
        v.y = fminf(fmaxf(fmaf(v.y, scale, off), -2.5f), 2.5f);             \
        v.z = fminf(fmaxf(fmaf(v.z, scale, off), -2.5f), 2.5f);             \
        v.w = fminf(fmaxf(fmaf(v.w, scale, off), -2.5f), 2.5f);
    XFORM(v0, off0)
    XFORM(v1, off1)
    XFORM(v2, off2)
    #undef XFORM

    float4* __restrict__ out4 =
        reinterpret_cast<float4*>(out) + (size_t)b * 3 * HW4;
    __stcs(&out4[0 * HW4 + p], v0);
    __stcs(&out4[1 * HW4 + p], v1);
    __stcs(&out4[2 * HW4 + p], v2);
}

extern "C" void kernel_launch(void* const* d_in, const int* in_sizes, int n_in,
                              void* d_out, int out_size) {
    const float* x   = (const float*)d_in[0];
    const float* br  = (const float*)d_in[1];
    const float* cfv = (const float*)d_in[2];
    const int*   fm  = (const int*)d_in[3];
    const int*   gm  = (const int*)d_in[4];
    const int*   ca  = (const int*)d_in[5];
    float* out = (float*)d_out;

    dim3 grid(NSL, B_);                                  // (49, 256)
    sum_and_easy_kernel<<<grid, 256>>>(x, br, fm, gm, ca, out);

    // Kernel C launched with programmatic dependent launch: it may begin
    // before A fully completes; correctness gated by GridDependencySync.
    cudaLaunchConfig_t cfg = {};
    cfg.gridDim  = grid;
    cfg.blockDim = dim3(256, 1, 1);
    cfg.stream   = 0;
    cudaLaunchAttribute attr[1];
    attr[0].id = cudaLaunchAttributeProgrammaticStreamSerialization;
    attr[0].val.programmaticStreamSerializationAllowed = 1;
    cfg.attrs    = attr;
    cfg.numAttrs = 1;
    cudaLaunchKernelEx(&cfg, contrast_kernel, x, br, cfv, fm, gm, ca, out);
}

// round 13
// speedup vs baseline: 1.0146x; 1.0146x over previous
#include <cuda_runtime.h>

#define B_   256
#define C_   3
#define H_   224
#define W_   224
#define HW_  (H_ * W_)          // 50176
#define HW4  (HW_ / 4)          // 12544 float4 per plane
#define NSL  49                 // slices per image (CTAs in x)

#define GW0 0.2989f
#define GW1 0.587f
#define GW2 0.114f

// Deterministic scratch: per-(image,slice) channel partial sums.
__device__ float g_part[B_ * NSL * 3];

// ---------------------------------------------------------------------------
// Kernel A: read input ONCE; per-slice channel sums. Non-contrast images are
// finished here (clip(aug(x)*br)). Contrast-image input is read evict-NORMAL
// (__ldcg) so it survives in L2 for kernel C. No explicit PDL trigger: the
// implicit completion (all CTAs drained) gates C, so C's launch overhead
// overlaps A's execution without competing for LTS bandwidth.
// ---------------------------------------------------------------------------
__global__ __launch_bounds__(256) void sum_and_easy_kernel(
    const float* __restrict__ x,
    const float* __restrict__ brightness,
    const int*   __restrict__ flip_mask,
    const int*   __restrict__ gray_mask,
    const int*   __restrict__ contrast_apply,
    float*       __restrict__ out)
{
    const int b   = blockIdx.y;
    const int sl  = blockIdx.x;
    const int tid = threadIdx.x;
    const int p   = sl * 256 + tid;                      // < HW4 (49*256)

    const float br   = brightness[b];
    const bool  flip = flip_mask[b] != 0;
    const bool  gray = gray_mask[b] != 0;
    const bool  ctr  = contrast_apply[b] != 0;

    // flip-aware source (sum is flip-invariant)
    const int pix = p * 4;
    const int h   = pix / W_;
    const int w   = pix - h * W_;
    const int sp4 = flip ? ((h * W_ + (W_ - 4 - w)) >> 2) : p;

    const float4* __restrict__ in4 =
        reinterpret_cast<const float4*>(x) + (size_t)b * 3 * HW4;

    float4 v0, v1, v2;
    if (ctr) {      // keep resident in L2 for kernel C
        v0 = __ldcg(&in4[0 * HW4 + sp4]);
        v1 = __ldcg(&in4[1 * HW4 + sp4]);
        v2 = __ldcg(&in4[2 * HW4 + sp4]);
    } else {        // dead after this kernel
        v0 = __ldcs(&in4[0 * HW4 + sp4]);
        v1 = __ldcs(&in4[1 * HW4 + sp4]);
        v2 = __ldcs(&in4[2 * HW4 + sp4]);
    }

    // per-channel partial sums of ORIGINAL x
    float s0 = (v0.x + v0.y) + (v0.z + v0.w);
    float s1 = (v1.x + v1.y) + (v1.z + v1.w);
    float s2 = (v2.x + v2.y) + (v2.z + v2.w);
    #pragma unroll
    for (int o = 16; o; o >>= 1) {
        s0 += __shfl_xor_sync(~0u, s0, o);
        s1 += __shfl_xor_sync(~0u, s1, o);
        s2 += __shfl_xor_sync(~0u, s2, o);
    }
    __shared__ float red[3][8];
    if ((tid & 31) == 0) {
        red[0][tid >> 5] = s0; red[1][tid >> 5] = s1; red[2][tid >> 5] = s2;
    }
    __syncthreads();
    if (tid == 0) {
        float a0 = 0.f, a1 = 0.f, a2 = 0.f;
        #pragma unroll
        for (int q = 0; q < 8; q++) { a0 += red[0][q]; a1 += red[1][q]; a2 += red[2][q]; }
        const int off = (b * NSL + sl) * 3;
        g_part[off + 0] = a0; g_part[off + 1] = a1; g_part[off + 2] = a2;
    }

    if (ctr) return;                                     // finished in kernel C

    // ---- no-contrast path: out = clip(aug(x)*br) ----
    if (flip) {
        float t;
        t = v0.x; v0.x = v0.w; v0.w = t;  t = v0.y; v0.y = v0.z; v0.z = t;
        t = v1.x; v1.x = v1.w; v1.w = t;  t = v1.y; v1.y = v1.z; v1.z = t;
        t = v2.x; v2.x = v2.w; v2.w = t;  t = v2.y; v2.y = v2.z; v2.z = t;
    }
    if (gray) {
        float4 g;
        g.x = GW0 * v0.x + GW1 * v1.x + GW2 * v2.x;
        g.y = GW0 * v0.y + GW1 * v1.y + GW2 * v2.y;
        g.z = GW0 * v0.z + GW1 * v1.z + GW2 * v2.z;
        g.w = GW0 * v0.w + GW1 * v1.w + GW2 * v2.w;
        v0 = g; v1 = g; v2 = g;
    }
    #define XFB(v)                                                           \
        v.x = fminf(fmaxf(v.x * br, -2.5f), 2.5f);                           \
        v.y = fminf(fmaxf(v.y * br, -2.5f), 2.5f);                           \
        v.z = fminf(fmaxf(v.z * br, -2.5f), 2.5f);                           \
        v.w = fminf(fmaxf(v.w * br, -2.5f), 2.5f);
    XFB(v0) XFB(v1) XFB(v2)
    #undef XFB

    float4* __restrict__ out4 =
        reinterpret_cast<float4*>(out) + (size_t)b * 3 * HW4;
    __stcs(&out4[0 * HW4 + p], v0);
    __stcs(&out4[1 * HW4 + p], v1);
    __stcs(&out4[2 * HW4 + p], v2);
}

// ---------------------------------------------------------------------------
// Kernel C: contrast images only. 128 threads per CTA, 2 pixels per thread
// (6 independent loads -> MLP 6, hides L2-hit latency). Non-contrast CTAs
// exit immediately (no dep-sync needed: they only read harness inputs).
// ---------------------------------------------------------------------------
__global__ __launch_bounds__(128) void contrast_kernel(
    const float* __restrict__ x,
    const float* __restrict__ brightness,
    const float* __restrict__ contrast_factor,
    const int*   __restrict__ flip_mask,
    const int*   __restrict__ gray_mask,
    const int*   __restrict__ contrast_apply,
    float*       __restrict__ out)
{
    const int b = blockIdx.y;
    if (contrast_apply[b] == 0) return;

    const int tid = threadIdx.x;
    const int p0  = blockIdx.x * 256 + tid;              // pixel A of this thread
    const int p1  = p0 + 128;                            // pixel B of this thread

    const float br   = brightness[b];
    const bool  flip = flip_mask[b] != 0;
    const bool  gray = gray_mask[b] != 0;
    const float cf   = contrast_factor[b];

    // A's g_part writes must be visible before the reduction.
    cudaGridDependencySynchronize();

    // flip-aware sources
    const int pixA = p0 * 4, hA = pixA / W_, wA = pixA - hA * W_;
    const int pixB = p1 * 4, hB = pixB / W_, wB = pixB - hB * W_;
    const int spA  = flip ? ((hA * W_ + (W_ - 4 - wA)) >> 2) : p0;
    const int spB  = flip ? ((hB * W_ + (W_ - 4 - wB)) >> 2) : p1;

    const float4* __restrict__ in4 =
        reinterpret_cast<const float4*>(x) + (size_t)b * 3 * HW4;
    // 6 independent loads in flight (L2-hot from kernel A)
    float4 a0 = __ldcs(&in4[0 * HW4 + spA]);
    float4 a1 = __ldcs(&in4[1 * HW4 + spA]);
    float4 a2 = __ldcs(&in4[2 * HW4 + spA]);
    float4 b0 = __ldcs(&in4[0 * HW4 + spB]);
    float4 b1 = __ldcs(&in4[1 * HW4 + spB]);
    float4 b2 = __ldcs(&in4[2 * HW4 + spB]);

    // cooperative per-CTA mean reduction (3 warps, deterministic, L2-hot)
    __shared__ float sm_mean[3];
    if (tid < 96) {
        const int c    = tid >> 5;
        const int lane = tid & 31;
        float s = 0.f;
        if (lane < NSL)      s  = g_part[(b * NSL + lane) * 3 + c];
        if (lane + 32 < NSL) s += g_part[(b * NSL + lane + 32) * 3 + c];
        #pragma unroll
        for (int o = 16; o; o >>= 1)
            s += __shfl_xor_sync(~0u, s, o);
        if (lane == 0)
            sm_mean[c] = s * (1.0f / (float)HW_);
    }
    __syncthreads();

    const float m0 = sm_mean[0];
    const float m1 = sm_mean[1];
    const float m2 = sm_mean[2];
    const float gm = GW0 * m0 + GW1 * m1 + GW2 * m2;

    const float mm0 = (gray ? gm : m0) * br;
    const float mm1 = (gray ? gm : m1) * br;
    const float mm2 = (gray ? gm : m2) * br;

    const float scale = br * cf;
    const float omcf  = 1.0f - cf;
    const float off0 = mm0 * omcf;
    const float off1 = mm1 * omcf;
    const float off2 = mm2 * omcf;

    #define REV(v) { float t;                                                \
        t = v.x; v.x = v.w; v.w = t;  t = v.y; v.y = v.z; v.z = t; }
    if (flip) {
        REV(a0) REV(a1) REV(a2) REV(b0) REV(b1) REV(b2)
    }
    #undef REV

    if (gray) {
        float4 g;
        g.x = GW0*a0.x + GW1*a1.x + GW2*a2.x;
        g.y = GW0*a0.y + GW1*a1.y + GW2*a2.y;
        g.z = GW0*a0.z + GW1*a1.z + GW2*a2.z;
        g.w = GW0*a0.w + GW1*a1.w + GW2*a2.w;
        a0 = g; a1 = g; a2 = g;
        g.x = GW0*b0.x + GW1*b1.x + GW2*b2.x;
        g.y = GW0*b0.y + GW1*b1.y + GW2*b2.y;
        g.z = GW0*b0.z + GW1*b1.z + GW2*b2.z;
        g.w = GW0*b0.w + GW1*b1.w + GW2*b2.w;
        b0 = g; b1 = g; b2 = g;
    }

    #define XFORM(v, off)                                                    \
        v.x = fminf(fmaxf(fmaf(v.x, scale, off), -2.5f), 2.5f);             \
        v.y = fminf(fmaxf(fmaf(v.y, scale, off), -2.5f), 2.5f);             \
        v.z = fminf(fmaxf(fmaf(v.z, scale, off), -2.5f), 2.5f);             \
        v.w = fminf(fmaxf(fmaf(v.w, scale, off), -2.5f), 2.5f);
    XFORM(a0, off0) XFORM(a1, off1) XFORM(a2, off2)
    XFORM(b0, off0) XFORM(b1, off1) XFORM(b2, off2)
    #undef XFORM

    float4* __restrict__ out4 =
        reinterpret_cast<float4*>(out) + (size_t)b * 3 * HW4;
    __stcs(&out4[0 * HW4 + p0], a0);
    __stcs(&out4[1 * HW4 + p0], a1);
    __stcs(&out4[2 * HW4 + p0], a2);
    __stcs(&out4[0 * HW4 + p1], b0);
    __stcs(&out4[1 * HW4 + p1], b1);
    __stcs(&out4[2 * HW4 + p1], b2);
}

extern "C" void kernel_launch(void* const* d_in, const int* in_sizes, int n_in,
                              void* d_out, int out_size) {
    const float* x   = (const float*)d_in[0];
    const float* br  = (const float*)d_in[1];
    const float* cfv = (const float*)d_in[2];
    const int*   fm  = (const int*)d_in[3];
    const int*   gm  = (const int*)d_in[4];
    const int*   ca  = (const int*)d_in[5];
    float* out = (float*)d_out;

    dim3 grid(NSL, B_);                                  // (49, 256)
    sum_and_easy_kernel<<<grid, 256>>>(x, br, fm, gm, ca, out);

    // PDL launch: C's setup overlaps A's execution; C's work starts when A
    // drains (implicit completion — A never calls the explicit trigger).
    cudaLaunchConfig_t cfg = {};
    cfg.gridDim  = grid;                                 // (49, 256), 128 thr
    cfg.blockDim = dim3(128, 1, 1);
    cfg.stream   = 0;
    cudaLaunchAttribute attr[1];
    attr[0].id = cudaLaunchAttributeProgrammaticStreamSerialization;
    attr[0].val.programmaticStreamSerializationAllowed = 1;
    cfg.attrs    = attr;
    cfg.numAttrs = 1;
    cudaLaunchKernelEx(&cfg, contrast_kernel, x, br, cfv, fm, gm, ca, out);
}